// round 17
// baseline (speedup 1.0000x reference)
#include <cuda_runtime.h>
#include <math.h>
#include <stdint.h>

// Problem dims
#define Bk 64
#define Tk 256
#define Dk 512
#define Hk 1024
#define Gk 3072
#define Ok 64
#define BT 16384

#define NB 128    // persistent blocks, one per 8 h-columns; all co-resident (1/SM)

typedef unsigned long long ull;

// -------- device scratch (no allocation allowed; __device__ globals)
__device__ float g_hsT[(long)Tk * Hk * Bk];   // [t][k][b] transposed h (64 MB)

__device__ unsigned g_bar_count;              // init barrier
__device__ volatile unsigned g_bar_gen;       // init barrier (replay-safe)
__device__ volatile unsigned g_flags[NB];     // flag barrier arrivals
__device__ volatile unsigned g_rel;           // flag barrier release

// -------- packed f32x2 helpers (FFMA2: 2x fp32 FMA throughput, exact fp32)
__device__ __forceinline__ ull ffma2(ull a, ull b, ull c) {
  ull d;
  asm("fma.rn.f32x2 %0, %1, %2, %3;" : "=l"(d) : "l"(a), "l"(b), "l"(c));
  return d;
}
__device__ __forceinline__ ull pack2(float lo, float hi) {
  ull d; asm("mov.b64 %0, {%1, %2};" : "=l"(d) : "f"(lo), "f"(hi)); return d;
}
__device__ __forceinline__ float2 unpack2(ull v) {
  float2 r; asm("mov.b64 {%0, %1}, %2;" : "=f"(r.x), "=f"(r.y) : "l"(v)); return r;
}
__device__ __forceinline__ float sigmoidf_(float x) { return 1.0f / (1.0f + expf(-x)); }

__device__ __forceinline__ void cp16(uint32_t dst, const float* src) {
  asm volatile("cp.async.cg.shared.global [%0], [%1], 16;" :: "r"(dst), "l"(src));
}
__device__ __forceinline__ void cp_commit() { asm volatile("cp.async.commit_group;"); }

// ---- smem layout (floats). Total 53952 floats = 215808 B (~210.8 KB)
//      EMB stride is 66 (EVEN — round-16's 65 made d*65+2*pb odd for odd d,
//      so LDS.64 trapped on 4B alignment: the "misaligned address" crash).
#define SM_WHH 0        // [1024 k][24 rows]            24576
#define SM_WIH 24576    // [512 d][24 cols]             12288
#define SM_HS  36864    // [2 buf][4 q][8 k][64 b]       4096
#define SM_P   40960    // [4 s][64 b][26]               6656
#define SM_HP  47616    // [64 b][8 jl]                   512
#define SM_GX  48128    // [64 b][24 cols]               1536
#define SM_EMB 49664    // [2 buf][32 d][66]             4224
#define SM_TOK 53888    // 64 ints
#define SM_TOTAL 53952

__device__ __forceinline__ void init_bar() {
  __threadfence();
  __syncthreads();
  if (threadIdx.x == 0) {
    unsigned my = g_bar_gen;
    if (atomicAdd(&g_bar_count, 1u) == NB - 1) {
      g_bar_count = 0;
      __threadfence();
      g_bar_gen = my + 1;
    } else {
      while (g_bar_gen == my) { }
      __threadfence();
    }
  }
  __syncthreads();
}

// ============================================================================
// Persistent fused GRU: gates GEMM folded INTO the step (no standalone gates
// kernel, no 201MB g_gates). Block g computes + consumes its own 24 gate-cols.
// Gates for step t+1 are computed BETWEEN barrier arrive and release-wait:
// warps 0-3 do the FFMA chains, warps 4-7 stream emb chunks (LDG+STS
// transpose). All FP chain orders identical to the passing kernels:
//   gates: one ascending d=0..511 chain per output, bias at end;
//   h-GEMM: 4 k-quarter chains (8k-chunks ascending), smem left-fold s=0..3.
// ============================================================================
__global__ __launch_bounds__(256, 1) void gru_persistent(
    const int* __restrict__ x, const float* __restrict__ emb,
    const float* __restrict__ W_ih, const float* __restrict__ b_ih,
    const float* __restrict__ W_hh, const float* __restrict__ b_hh) {
  extern __shared__ float smem[];
  float* Whh   = smem + SM_WHH;
  float* Wih   = smem + SM_WIH;
  float* HsBuf = smem + SM_HS;
  float* P     = smem + SM_P;
  float* Hprev = smem + SM_HP;
  float* GXs   = smem + SM_GX;
  float* EmbS  = smem + SM_EMB;
  int*   tokS  = (int*)(smem + SM_TOK);

  const int tid = threadIdx.x;
  const int g = blockIdx.x;            // h-cols g*8..g*8+7
  const int q = tid >> 6;              // k-quarter 0..3 (h-GEMM)
  const int l = tid & 63;
  const int m0 = (l & 15) << 2;        // 4 batch rows
  const int n0 = (l >> 4) * 6;         // 6 local cols (3 f32x2 pairs)
  const int jl = tid & 7;              // gate-stage local h-col
  const int b0g = tid >> 3;            // gate-stage batch (and +32)
  const int pb = tid & 31;             // gates: b-pair (b0=2*pb)
  const int cg0 = (tid >> 5) * 6;      // gates: col group (tid<128)

  if (g == 0) {
    if (tid < NB) g_flags[tid] = 0;
    if (tid == 0) g_rel = 0;
  }

  // ---- W_hh slice: [1024 k][24 rows], row L=e*8+c -> W_hh[e*1024+g*8+c]
  for (int i = tid; i < 24 * 256; i += 256) {
    int L = i >> 8, f4 = i & 255;
    int e = L >> 3, c = L & 7;
    float4 v = *reinterpret_cast<const float4*>(
        &W_hh[(long)(e * Hk + g * 8 + c) * Hk + f4 * 4]);
    int kk = f4 * 4;
    Whh[(kk + 0) * 24 + L] = v.x;
    Whh[(kk + 1) * 24 + L] = v.y;
    Whh[(kk + 2) * 24 + L] = v.z;
    Whh[(kk + 3) * 24 + L] = v.w;
  }
  // ---- W_ih slice: [512 d][24 cols], col L -> W_ih row (L>>3)*1024+g*8+(L&7)
  for (int i = tid; i < 24 * 128; i += 256) {
    int L = i >> 7, f4 = i & 127;
    float4 v = *reinterpret_cast<const float4*>(
        &W_ih[(long)((L >> 3) * Hk + g * 8 + (L & 7)) * Dk + f4 * 4]);
    int dd = f4 * 4;
    Wih[(dd + 0) * 24 + L] = v.x;
    Wih[(dd + 1) * 24 + L] = v.y;
    Wih[(dd + 2) * 24 + L] = v.z;
    Wih[(dd + 3) * 24 + L] = v.w;
  }
  const float bh0 = b_hh[g * 8 + jl];
  const float bh1 = b_hh[Hk + g * 8 + jl];
  const float bh2 = b_hh[2 * Hk + g * 8 + jl];
  float gbias[6];
#pragma unroll
  for (int i = 0; i < 6; i++) {
    int L = cg0 + i;   // meaningful for tid<128; harmless otherwise
    gbias[i] = b_ih[(L >> 3) * Hk + g * 8 + (L & 7)];
  }

  init_bar();   // flag resets visible before any arrival
  __syncthreads();

  const uint32_t hsbuf_s =
      (uint32_t)__cvta_generic_to_shared(HsBuf);

// ---- gates GEMM for step tt: fills GXs[64b][24c].
//      warps 4-7 stream 16 emb chunks (32 d each, transposed [d][66]);
//      warps 0-3: 2 b x 6 c per thread, single ascending-d FFMA chain.
#define GATES_PHASE(tt)                                                        \
  {                                                                            \
    if (tid >= 192) tokS[tid - 192] = x[(tid - 192) * Tk + (tt)];              \
    __syncthreads();                                                           \
    ull gacc[6] = {0, 0, 0, 0, 0, 0};                                          \
    if (tid >= 128) {  /* fill chunk 0 */                                      \
      int u = tid - 128, r = u & 63, fq = (u >> 6) * 4;                        \
      const float4* s4 = reinterpret_cast<const float4*>(emb) +                \
                         (long)tokS[r] * 128 + fq;                             \
      float* Eb = EmbS;                                                        \
      for (int j = 0; j < 4; j++) {                                            \
        float4 v = s4[j];                                                      \
        int dd = (fq + j) * 4;                                                 \
        Eb[(dd + 0) * 66 + r] = v.x; Eb[(dd + 1) * 66 + r] = v.y;              \
        Eb[(dd + 2) * 66 + r] = v.z; Eb[(dd + 3) * 66 + r] = v.w;              \
      }                                                                        \
    }                                                                          \
    __syncthreads();                                                           \
    for (int c = 0; c < 16; c++) {                                             \
      if (tid >= 128) {                                                        \
        if (c < 15) {                                                          \
          int u = tid - 128, r = u & 63, fq = (u >> 6) * 4;                    \
          const float4* s4 = reinterpret_cast<const float4*>(emb) +            \
                             (long)tokS[r] * 128 + (c + 1) * 8 + fq;           \
          float* Eb = EmbS + ((c + 1) & 1) * 2112;                             \
          for (int j = 0; j < 4; j++) {                                        \
            float4 v = s4[j];                                                  \
            int dd = (fq + j) * 4;                                             \
            Eb[(dd + 0) * 66 + r] = v.x; Eb[(dd + 1) * 66 + r] = v.y;          \
            Eb[(dd + 2) * 66 + r] = v.z; Eb[(dd + 3) * 66 + r] = v.w;          \
          }                                                                    \
        }                                                                      \
      } else {                                                                 \
        const float* Eb = EmbS + (c & 1) * 2112;                               \
        const float* Wd = Wih + (c * 32) * 24 + cg0;                           \
        _Pragma("unroll")                                                      \
        for (int d = 0; d < 32; d++) {                                         \
          float2 e2 = *reinterpret_cast<const float2*>(&Eb[d * 66 + 2 * pb]);  \
          const float* wr = Wd + d * 24;                                       \
          ull w01 = *reinterpret_cast<const ull*>(wr);                         \
          ull w23 = *reinterpret_cast<const ull*>(wr + 2);                     \
          ull w45 = *reinterpret_cast<const ull*>(wr + 4);                     \
          ull a0 = pack2(e2.x, e2.x), a1 = pack2(e2.y, e2.y);                  \
          gacc[0] = ffma2(a0, w01, gacc[0]);                                   \
          gacc[1] = ffma2(a0, w23, gacc[1]);                                   \
          gacc[2] = ffma2(a0, w45, gacc[2]);                                   \
          gacc[3] = ffma2(a1, w01, gacc[3]);                                   \
          gacc[4] = ffma2(a1, w23, gacc[4]);                                   \
          gacc[5] = ffma2(a1, w45, gacc[5]);                                   \
        }                                                                      \
      }                                                                        \
      __syncthreads();                                                         \
    }                                                                          \
    if (tid < 128) {                                                           \
      _Pragma("unroll")                                                        \
      for (int bb2 = 0; bb2 < 2; bb2++)                                        \
        _Pragma("unroll")                                                      \
        for (int cp = 0; cp < 3; cp++) {                                       \
          float2 u = unpack2(gacc[bb2 * 3 + cp]);                              \
          u.x += gbias[2 * cp]; u.y += gbias[2 * cp + 1];                      \
          *reinterpret_cast<float2*>(                                          \
              &GXs[(2 * pb + bb2) * 24 + cg0 + 2 * cp]) = u;                   \
        }                                                                      \
    }                                                                          \
  }

  GATES_PHASE(0);        // prologue: gates for t=0
  __syncthreads();

  for (int t = 0; t < Tk; t++) {
    if (t > 0) {
      // ---- h-GEMM: 32 chunks of 8k, double-buffered cp.async
      const float* src = g_hsT + (long)(t - 1) * (Hk * Bk) + q * 16384;
      {
        uint32_t dst = hsbuf_s + (uint32_t)((q * 512 + l * 8) * 4);
        cp16(dst, src + l * 8);
        cp16(dst + 16, src + l * 8 + 4);
        cp_commit();
      }
      ull acc[4][3] = {};
#pragma unroll 1
      for (int i = 0; i < 32; i++) {
        asm volatile("cp.async.wait_group 0;" ::: "memory");
        __syncthreads();
        if (i < 31) {
          int bf = (i + 1) & 1;
          uint32_t dst =
              hsbuf_s + (uint32_t)((bf * 2048 + q * 512 + l * 8) * 4);
          const float* s1 = src + (i + 1) * 512 + l * 8;
          cp16(dst, s1);
          cp16(dst + 16, s1 + 4);
          cp_commit();
        }
        const float* A = HsBuf + (i & 1) * 2048 + q * 512;
        const float* Bw = Whh + (q * 256 + i * 8) * 24;
#pragma unroll
        for (int kk = 0; kk < 8; kk++) {
          float4 av = *reinterpret_cast<const float4*>(&A[kk * 64 + m0]);
          const float* wr = &Bw[kk * 24 + n0];
          ull w0 = *reinterpret_cast<const ull*>(wr);
          ull w1 = *reinterpret_cast<const ull*>(wr + 2);
          ull w2 = *reinterpret_cast<const ull*>(wr + 4);
          ull a0 = pack2(av.x, av.x), a1 = pack2(av.y, av.y);
          ull a2 = pack2(av.z, av.z), a3 = pack2(av.w, av.w);
          acc[0][0] = ffma2(a0, w0, acc[0][0]);
          acc[0][1] = ffma2(a0, w1, acc[0][1]);
          acc[0][2] = ffma2(a0, w2, acc[0][2]);
          acc[1][0] = ffma2(a1, w0, acc[1][0]);
          acc[1][1] = ffma2(a1, w1, acc[1][1]);
          acc[1][2] = ffma2(a1, w2, acc[1][2]);
          acc[2][0] = ffma2(a2, w0, acc[2][0]);
          acc[2][1] = ffma2(a2, w1, acc[2][1]);
          acc[2][2] = ffma2(a2, w2, acc[2][2]);
          acc[3][0] = ffma2(a3, w0, acc[3][0]);
          acc[3][1] = ffma2(a3, w1, acc[3][1]);
          acc[3][2] = ffma2(a3, w2, acc[3][2]);
        }
      }
      // ---- quarter partials -> P (stride 26)
#pragma unroll
      for (int m = 0; m < 4; m++) {
        float* pp = &P[(q * 64 + m0 + m) * 26 + n0];
#pragma unroll
        for (int p = 0; p < 3; p++)
          *reinterpret_cast<float2*>(pp + 2 * p) = unpack2(acc[m][p]);
      }
      __syncthreads();
    }

    // ---- gate stage: gx from smem GXs (bias already included)
#pragma unroll
    for (int r2 = 0; r2 < 2; r2++) {
      int bb = b0g + r2 * 32;
      float gx0 = GXs[bb * 24 + jl];
      float gx1 = GXs[bb * 24 + 8 + jl];
      float gx2 = GXs[bb * 24 + 16 + jl];
      float hr = 0.0f, hz = 0.0f, hn = 0.0f;
      if (t > 0) {
#pragma unroll
        for (int s = 0; s < 4; s++) {   // left fold s=0..3 (identical order)
          const float* pp = &P[(s * 64 + bb) * 26];
          hr += pp[jl];
          hz += pp[8 + jl];
          hn += pp[16 + jl];
        }
      }
      float rr = sigmoidf_(gx0 + hr + bh0);
      float zz = sigmoidf_(gx1 + hz + bh1);
      float nn = tanhf(gx2 + rr * (hn + bh2));
      float hp = (t == 0) ? 0.0f : Hprev[bb * 8 + jl];
      float hnew = (1.0f - zz) * nn + zz * hp;
      Hprev[bb * 8 + jl] = hnew;
      g_hsT[(long)t * (Hk * Bk) + (g * 8 + jl) * 64 + bb] = hnew;
    }

    // ---- barrier ARRIVE (h(t) published), then productive wait:
    __syncthreads();
    if (tid == 0) { __threadfence(); g_flags[g] = (unsigned)(t + 1); }

    if (t + 1 < Tk) GATES_PHASE(t + 1);   // fills the barrier-wait window

    // ---- barrier WAIT (release fan-out, R11-proven)
    if (g == 0) {
      if (tid < NB) { while (g_flags[tid] < (unsigned)(t + 1)) { } }
      __syncthreads();
      if (tid == 0) { __threadfence(); g_rel = (unsigned)(t + 1); }
      __syncthreads();
    } else {
      if (tid == 0) {
        while (g_rel < (unsigned)(t + 1)) { }
        __threadfence();
      }
      __syncthreads();
    }
  }
}

// ============================================================================
// fc (round-11 verbatim): logits = hs @ W_fc^T + b_fc; sigmoid; labels.
//   label = (computed fp32 proba > 0.5f) — matches reference rounding exactly.
// ============================================================================
__global__ __launch_bounds__(256) void fc_kernel(const float* __restrict__ W_fc,
                                                 const float* __restrict__ b_fc,
                                                 float* __restrict__ out,
                                                 int write_labels) {
  __shared__ __align__(16) float Hs[32][64];
  __shared__ __align__(16) float Ws[32][64];

  const int t = blockIdx.x;
  const int tid = threadIdx.x;
  const float* __restrict__ hbT = g_hsT + (long)t * (Hk * Bk);

  ull acc[2][4] = {};
  const int m0 = (tid & 15) * 4;
  const int n0 = (tid >> 4) * 4;
  const int kr = tid >> 4, f4i = tid & 15;

  for (int kc = 0; kc < Hk; kc += 32) {
#pragma unroll
    for (int u = 0; u < 2; u++) {
      int kk = kr + u * 16;
      float4 v = *reinterpret_cast<const float4*>(&hbT[(long)(kc + kk) * 64 + f4i * 4]);
      *reinterpret_cast<float4*>(&Hs[kk][f4i * 4]) = v;
    }
#pragma unroll
    for (int i = 0; i < 2; i++) {
      int n = (tid >> 3) + i * 32;
      int f4 = tid & 7;
      float4 w = *reinterpret_cast<const float4*>(&W_fc[(long)n * Hk + kc + f4 * 4]);
      Ws[f4 * 4 + 0][n] = w.x; Ws[f4 * 4 + 1][n] = w.y;
      Ws[f4 * 4 + 2][n] = w.z; Ws[f4 * 4 + 3][n] = w.w;
    }
    __syncthreads();

#pragma unroll
    for (int k = 0; k < 32; k++) {
      const ull* ap = reinterpret_cast<const ull*>(&Hs[k][m0]);
      ull a0 = ap[0], a1 = ap[1];
      float4 bv = *reinterpret_cast<const float4*>(&Ws[k][n0]);
      ull bb[4];
      bb[0] = pack2(bv.x, bv.x); bb[1] = pack2(bv.y, bv.y);
      bb[2] = pack2(bv.z, bv.z); bb[3] = pack2(bv.w, bv.w);
#pragma unroll
      for (int j = 0; j < 4; j++) {
        acc[0][j] = ffma2(a0, bb[j], acc[0][j]);
        acc[1][j] = ffma2(a1, bb[j], acc[1][j]);
      }
    }
    __syncthreads();
  }

  const float bs0 = b_fc[n0 + 0], bs1 = b_fc[n0 + 1];
  const float bs2 = b_fc[n0 + 2], bs3 = b_fc[n0 + 3];
#pragma unroll
  for (int i = 0; i < 2; i++) {
    float2 u0 = unpack2(acc[i][0]), u1 = unpack2(acc[i][1]);
    float2 u2 = unpack2(acc[i][2]), u3 = unpack2(acc[i][3]);
    float lg[2][4] = {
        {u0.x + bs0, u1.x + bs1, u2.x + bs2, u3.x + bs3},
        {u0.y + bs0, u1.y + bs1, u2.y + bs2, u3.y + bs3}};
#pragma unroll
    for (int p = 0; p < 2; p++) {
      int b = m0 + 2 * i + p;
      long base = ((long)b * Tk + t) * Ok + n0;
      float4 pr = make_float4(sigmoidf_(lg[p][0]), sigmoidf_(lg[p][1]),
                              sigmoidf_(lg[p][2]), sigmoidf_(lg[p][3]));
      *reinterpret_cast<float4*>(&out[base]) = pr;
      if (write_labels) {
        float4 lb = make_float4(pr.x > 0.5f ? 1.0f : 0.0f,
                                pr.y > 0.5f ? 1.0f : 0.0f,
                                pr.z > 0.5f ? 1.0f : 0.0f,
                                pr.w > 0.5f ? 1.0f : 0.0f);
        *reinterpret_cast<float4*>(&out[(long)BT * Ok + base]) = lb;
      }
    }
  }
}

// ============================================================================
// Launch: graph-capturable (kernel launches only, deterministic, no allocs)
// ============================================================================
extern "C" void kernel_launch(void* const* d_in, const int* in_sizes, int n_in,
                              void* d_out, int out_size) {
  const int*   x    = (const int*)d_in[0];
  const float* emb  = (const float*)d_in[1];
  const float* W_ih = (const float*)d_in[2];
  const float* W_hh = (const float*)d_in[3];
  const float* b_ih = (const float*)d_in[4];
  const float* b_hh = (const float*)d_in[5];
  const float* W_fc = (const float*)d_in[6];
  const float* b_fc = (const float*)d_in[7];
  float* out = (float*)d_out;

  const int smem_bytes = SM_TOTAL * (int)sizeof(float);   // 215808 B
  cudaFuncSetAttribute(gru_persistent,
                       cudaFuncAttributeMaxDynamicSharedMemorySize, smem_bytes);

  gru_persistent<<<NB, 256, smem_bytes>>>(x, emb, W_ih, b_ih, W_hh, b_hh);

  const int write_labels = (out_size >= 2 * BT * Ok) ? 1 : 0;
  fc_kernel<<<256, 256>>>(W_fc, b_fc, out, write_labels);
}